// round 2
// baseline (speedup 1.0000x reference)
#include <cuda_runtime.h>

// Problem constants
#define T   2048
#define H   2048
#define NE  8
#define F   1408
#define FS  2816

// GEMM tiling
#define TM  64
#define TN  64
#define TKK 16
#define CAPTILES 72            // 4096/64 row tiles + 8 alignment pads
#define CAP (CAPTILES * TM)    // 4608 bucket slots

// ---------------- device scratch (no allocations allowed) ----------------
__device__ int   g_cnt[NE];
__device__ int   g_fill[NE];
__device__ int   g_seg[NE];
__device__ int   g_tidx[T * 2];
__device__ float g_tw[T * 2];
__device__ int   g_btok[CAP];
__device__ float g_bw[CAP];
__device__ float g_h1[(size_t)CAP * F];     // routed intermediate  (~26 MB)
__device__ float g_h1s[(size_t)T * FS];     // shared intermediate  (~23 MB)

// ---------------- f32x2 packed-FMA helpers (sm_103a FFMA2) ----------------
__device__ __forceinline__ unsigned long long pack_dup(float a) {
    unsigned long long r;
    asm("mov.b64 %0, {%1, %1};" : "=l"(r) : "f"(a));
    return r;
}
__device__ __forceinline__ void fma_x2(unsigned long long& acc,
                                       unsigned long long a,
                                       unsigned long long b) {
    asm("fma.rn.f32x2 %0, %1, %2, %0;" : "+l"(acc) : "l"(a), "l"(b));
}
__device__ __forceinline__ float2 unpack2(unsigned long long v) {
    float2 f;
    asm("mov.b64 {%0, %1}, %2;" : "=f"(f.x), "=f"(f.y) : "l"(v));
    return f;
}

// ---------------- small kernels ----------------
__global__ void k_init() {
    int i = threadIdx.x;
    if (i < NE) { g_cnt[i] = 0; g_fill[i] = 0; }
}

// one warp per token: logits over 8 experts, softmax, top-2, normalize
__global__ void k_gate(const float* __restrict__ x, const float* __restrict__ gw) {
    int gt   = blockIdx.x * blockDim.x + threadIdx.x;
    int t    = gt >> 5;
    int lane = gt & 31;
    if (t >= T) return;
    const float* xr = x + (size_t)t * H;
    float acc[NE];
#pragma unroll
    for (int e = 0; e < NE; e++) acc[e] = 0.f;
    for (int i = lane; i < H; i += 32) {
        float xv = xr[i];
#pragma unroll
        for (int e = 0; e < NE; e++) acc[e] += xv * gw[e * H + i];
    }
#pragma unroll
    for (int e = 0; e < NE; e++) {
#pragma unroll
        for (int o = 16; o > 0; o >>= 1)
            acc[e] += __shfl_down_sync(0xffffffffu, acc[e], o);
    }
    if (lane == 0) {
        float m = acc[0];
#pragma unroll
        for (int e = 1; e < NE; e++) m = fmaxf(m, acc[e]);
        float p[NE], s = 0.f;
#pragma unroll
        for (int e = 0; e < NE; e++) { p[e] = expf(acc[e] - m); s += p[e]; }
        float inv = 1.f / s;
#pragma unroll
        for (int e = 0; e < NE; e++) p[e] *= inv;
        int i0 = 0; float v0 = p[0];
#pragma unroll
        for (int e = 1; e < NE; e++) if (p[e] > v0) { v0 = p[e]; i0 = e; }
        int i1 = -1; float v1 = -1.f;
#pragma unroll
        for (int e = 0; e < NE; e++) if (e != i0 && p[e] > v1) { v1 = p[e]; i1 = e; }
        float d = 1.f / (v0 + v1 + 1e-20f);
        g_tidx[t * 2 + 0] = i0; g_tw[t * 2 + 0] = v0 * d;
        g_tidx[t * 2 + 1] = i1; g_tw[t * 2 + 1] = v1 * d;
        atomicAdd(&g_cnt[i0], 1);
        atomicAdd(&g_cnt[i1], 1);
    }
}

__global__ void k_scan() {
    if (threadIdx.x == 0) {
        int acc = 0;
        for (int e = 0; e < NE; e++) {
            g_seg[e] = acc;
            acc += (g_cnt[e] + TM - 1) / TM * TM;
        }
    }
}

__global__ void k_scatter() {
    int t = blockIdx.x * blockDim.x + threadIdx.x;
    if (t >= T) return;
#pragma unroll
    for (int k = 0; k < 2; k++) {
        int e   = g_tidx[t * 2 + k];
        float w = g_tw[t * 2 + k];
        int pos = atomicAdd(&g_fill[e], 1);
        int slot = g_seg[e] + pos;
        g_btok[slot] = t;
        g_bw[slot]   = w;
    }
}

// ---------------- expert lookup for a routed row tile ----------------
__device__ __forceinline__ void find_expert(int row0, int& e_out, int& valid_out) {
    int e = -1, vr = 0;
    for (int i = 0; i < NE; i++) {
        int st = g_seg[i];
        int sz = (g_cnt[i] + TM - 1) / TM * TM;
        if (row0 >= st && row0 < st + sz) { e = i; vr = g_cnt[i] - (row0 - st); break; }
    }
    e_out = e; valid_out = vr;
}

// ================= GEMM 1: routed gate+up, fused SiLU =================
// h1[slot, F] = silu(x[tok] @ wg_e^T) * (x[tok] @ wu_e^T)
__global__ __launch_bounds__(256) void k_routed_upgate(
    const float* __restrict__ x, const float* __restrict__ wg,
    const float* __restrict__ wu) {
    __shared__ float As[TKK][TM];
    __shared__ float B0[TKK][TN];
    __shared__ float B1[TKK][TN];
    __shared__ int   stok[TM];
    __shared__ int   sh_e, sh_valid;

    int tid  = threadIdx.x;
    int row0 = blockIdx.y * TM;
    if (tid == 0) find_expert(row0, sh_e, sh_valid);
    __syncthreads();
    int e = sh_e;
    if (e < 0 || sh_valid <= 0) return;
    int nvalid = sh_valid > TM ? TM : sh_valid;
    if (tid < TM) stok[tid] = (tid < nvalid) ? g_btok[row0 + tid] : 0;
    __syncthreads();

    int lr = tid >> 2, lq = tid & 3;
    int tx = tid & 15, ty = tid >> 4;
    int col0 = blockIdx.x * TN;
    int atok = stok[lr];
    const float* ap  = x  + (size_t)atok * H + lq * 4;
    const float* bgp = wg + (size_t)e * F * H + (size_t)(col0 + lr) * H + lq * 4;
    const float* bup = wu + (size_t)e * F * H + (size_t)(col0 + lr) * H + lq * 4;

    unsigned long long accg[4][2], accu[4][2];
#pragma unroll
    for (int i = 0; i < 4; i++)
#pragma unroll
        for (int j = 0; j < 2; j++) { accg[i][j] = 0ull; accu[i][j] = 0ull; }

    for (int k0 = 0; k0 < H; k0 += TKK) {
        float4 av = *(const float4*)(ap + k0);
        float4 bg = *(const float4*)(bgp + k0);
        float4 bu = *(const float4*)(bup + k0);
        __syncthreads();
        As[lq * 4 + 0][lr] = av.x; As[lq * 4 + 1][lr] = av.y;
        As[lq * 4 + 2][lr] = av.z; As[lq * 4 + 3][lr] = av.w;
        B0[lq * 4 + 0][lr] = bg.x; B0[lq * 4 + 1][lr] = bg.y;
        B0[lq * 4 + 2][lr] = bg.z; B0[lq * 4 + 3][lr] = bg.w;
        B1[lq * 4 + 0][lr] = bu.x; B1[lq * 4 + 1][lr] = bu.y;
        B1[lq * 4 + 2][lr] = bu.z; B1[lq * 4 + 3][lr] = bu.w;
        __syncthreads();
#pragma unroll
        for (int kk = 0; kk < TKK; kk++) {
            float4 a = *(const float4*)&As[kk][ty * 4];
            ulonglong2 b0 = *(const ulonglong2*)&B0[kk][tx * 4];
            ulonglong2 b1 = *(const ulonglong2*)&B1[kk][tx * 4];
            unsigned long long ad[4] = {pack_dup(a.x), pack_dup(a.y),
                                        pack_dup(a.z), pack_dup(a.w)};
#pragma unroll
            for (int i = 0; i < 4; i++) {
                fma_x2(accg[i][0], ad[i], b0.x);
                fma_x2(accg[i][1], ad[i], b0.y);
                fma_x2(accu[i][0], ad[i], b1.x);
                fma_x2(accu[i][1], ad[i], b1.y);
            }
        }
    }
#pragma unroll
    for (int i = 0; i < 4; i++) {
        int r = ty * 4 + i;
        if (r < nvalid) {
            float* dst = g_h1 + (size_t)(row0 + r) * F + col0 + tx * 4;
#pragma unroll
            for (int j = 0; j < 2; j++) {
                float2 g = unpack2(accg[i][j]);
                float2 u = unpack2(accu[i][j]);
                dst[j * 2 + 0] = g.x * (1.f / (1.f + expf(-g.x))) * u.x;
                dst[j * 2 + 1] = g.y * (1.f / (1.f + expf(-g.y))) * u.y;
            }
        }
    }
}

// ================= GEMM 2: routed down, weighted atomic accumulate =================
__global__ __launch_bounds__(256) void k_routed_down(
    const float* __restrict__ wd, float* __restrict__ out) {
    __shared__ float As[TKK][TM];
    __shared__ float Bs[TKK][TN];
    __shared__ int   stok[TM];
    __shared__ float swt[TM];
    __shared__ int   sh_e, sh_valid;

    int tid  = threadIdx.x;
    int row0 = blockIdx.y * TM;
    if (tid == 0) find_expert(row0, sh_e, sh_valid);
    __syncthreads();
    int e = sh_e;
    if (e < 0 || sh_valid <= 0) return;
    int nvalid = sh_valid > TM ? TM : sh_valid;
    if (tid < TM) {
        bool v = tid < nvalid;
        stok[tid] = v ? g_btok[row0 + tid] : 0;
        swt[tid]  = v ? g_bw[row0 + tid]  : 0.f;
    }
    __syncthreads();

    int lr = tid >> 2, lq = tid & 3;
    int tx = tid & 15, ty = tid >> 4;
    int col0 = blockIdx.x * TN;
    const float* ap = g_h1 + (size_t)(row0 + lr) * F + lq * 4;
    const float* bp = wd + (size_t)e * H * F + (size_t)(col0 + lr) * F + lq * 4;

    unsigned long long acc[4][2];
#pragma unroll
    for (int i = 0; i < 4; i++) { acc[i][0] = 0ull; acc[i][1] = 0ull; }

    for (int k0 = 0; k0 < F; k0 += TKK) {
        float4 av = *(const float4*)(ap + k0);
        float4 bv = *(const float4*)(bp + k0);
        __syncthreads();
        As[lq * 4 + 0][lr] = av.x; As[lq * 4 + 1][lr] = av.y;
        As[lq * 4 + 2][lr] = av.z; As[lq * 4 + 3][lr] = av.w;
        Bs[lq * 4 + 0][lr] = bv.x; Bs[lq * 4 + 1][lr] = bv.y;
        Bs[lq * 4 + 2][lr] = bv.z; Bs[lq * 4 + 3][lr] = bv.w;
        __syncthreads();
#pragma unroll
        for (int kk = 0; kk < TKK; kk++) {
            float4 a = *(const float4*)&As[kk][ty * 4];
            ulonglong2 b = *(const ulonglong2*)&Bs[kk][tx * 4];
            unsigned long long ad[4] = {pack_dup(a.x), pack_dup(a.y),
                                        pack_dup(a.z), pack_dup(a.w)};
#pragma unroll
            for (int i = 0; i < 4; i++) {
                fma_x2(acc[i][0], ad[i], b.x);
                fma_x2(acc[i][1], ad[i], b.y);
            }
        }
    }
#pragma unroll
    for (int i = 0; i < 4; i++) {
        int r = ty * 4 + i;
        if (r < nvalid) {
            int tkn = stok[r];
            float w = swt[r];
            float* o = out + (size_t)tkn * H + col0 + tx * 4;
#pragma unroll
            for (int j = 0; j < 2; j++) {
                float2 v = unpack2(acc[i][j]);
                atomicAdd(&o[j * 2 + 0], w * v.x);
                atomicAdd(&o[j * 2 + 1], w * v.y);
            }
        }
    }
}

// ================= GEMM 3: shared gate+up, fused SiLU =================
__global__ __launch_bounds__(256) void k_shared_upgate(
    const float* __restrict__ x, const float* __restrict__ swg,
    const float* __restrict__ swu) {
    __shared__ float As[TKK][TM];
    __shared__ float B0[TKK][TN];
    __shared__ float B1[TKK][TN];

    int tid = threadIdx.x;
    int row0 = blockIdx.y * TM;
    int col0 = blockIdx.x * TN;
    int lr = tid >> 2, lq = tid & 3;
    int tx = tid & 15, ty = tid >> 4;
    const float* ap  = x   + (size_t)(row0 + lr) * H + lq * 4;
    const float* bgp = swg + (size_t)(col0 + lr) * H + lq * 4;
    const float* bup = swu + (size_t)(col0 + lr) * H + lq * 4;

    unsigned long long accg[4][2], accu[4][2];
#pragma unroll
    for (int i = 0; i < 4; i++)
#pragma unroll
        for (int j = 0; j < 2; j++) { accg[i][j] = 0ull; accu[i][j] = 0ull; }

    for (int k0 = 0; k0 < H; k0 += TKK) {
        float4 av = *(const float4*)(ap + k0);
        float4 bg = *(const float4*)(bgp + k0);
        float4 bu = *(const float4*)(bup + k0);
        __syncthreads();
        As[lq * 4 + 0][lr] = av.x; As[lq * 4 + 1][lr] = av.y;
        As[lq * 4 + 2][lr] = av.z; As[lq * 4 + 3][lr] = av.w;
        B0[lq * 4 + 0][lr] = bg.x; B0[lq * 4 + 1][lr] = bg.y;
        B0[lq * 4 + 2][lr] = bg.z; B0[lq * 4 + 3][lr] = bg.w;
        B1[lq * 4 + 0][lr] = bu.x; B1[lq * 4 + 1][lr] = bu.y;
        B1[lq * 4 + 2][lr] = bu.z; B1[lq * 4 + 3][lr] = bu.w;
        __syncthreads();
#pragma unroll
        for (int kk = 0; kk < TKK; kk++) {
            float4 a = *(const float4*)&As[kk][ty * 4];
            ulonglong2 b0 = *(const ulonglong2*)&B0[kk][tx * 4];
            ulonglong2 b1 = *(const ulonglong2*)&B1[kk][tx * 4];
            unsigned long long ad[4] = {pack_dup(a.x), pack_dup(a.y),
                                        pack_dup(a.z), pack_dup(a.w)};
#pragma unroll
            for (int i = 0; i < 4; i++) {
                fma_x2(accg[i][0], ad[i], b0.x);
                fma_x2(accg[i][1], ad[i], b0.y);
                fma_x2(accu[i][0], ad[i], b1.x);
                fma_x2(accu[i][1], ad[i], b1.y);
            }
        }
    }
#pragma unroll
    for (int i = 0; i < 4; i++) {
        int r = ty * 4 + i;
        float* dst = g_h1s + (size_t)(row0 + r) * FS + col0 + tx * 4;
#pragma unroll
        for (int j = 0; j < 2; j++) {
            float2 g = unpack2(accg[i][j]);
            float2 u = unpack2(accu[i][j]);
            dst[j * 2 + 0] = g.x * (1.f / (1.f + expf(-g.x))) * u.x;
            dst[j * 2 + 1] = g.y * (1.f / (1.f + expf(-g.y))) * u.y;
        }
    }
}

// ================= GEMM 4: shared down, plain store (initializes out) =================
__global__ __launch_bounds__(256) void k_shared_down(
    const float* __restrict__ swd, float* __restrict__ out) {
    __shared__ float As[TKK][TM];
    __shared__ float Bs[TKK][TN];

    int tid = threadIdx.x;
    int row0 = blockIdx.y * TM;
    int col0 = blockIdx.x * TN;
    int lr = tid >> 2, lq = tid & 3;
    int tx = tid & 15, ty = tid >> 4;
    const float* ap = g_h1s + (size_t)(row0 + lr) * FS + lq * 4;
    const float* bp = swd   + (size_t)(col0 + lr) * FS + lq * 4;

    unsigned long long acc[4][2];
#pragma unroll
    for (int i = 0; i < 4; i++) { acc[i][0] = 0ull; acc[i][1] = 0ull; }

    for (int k0 = 0; k0 < FS; k0 += TKK) {
        float4 av = *(const float4*)(ap + k0);
        float4 bv = *(const float4*)(bp + k0);
        __syncthreads();
        As[lq * 4 + 0][lr] = av.x; As[lq * 4 + 1][lr] = av.y;
        As[lq * 4 + 2][lr] = av.z; As[lq * 4 + 3][lr] = av.w;
        Bs[lq * 4 + 0][lr] = bv.x; Bs[lq * 4 + 1][lr] = bv.y;
        Bs[lq * 4 + 2][lr] = bv.z; Bs[lq * 4 + 3][lr] = bv.w;
        __syncthreads();
#pragma unroll
        for (int kk = 0; kk < TKK; kk++) {
            float4 a = *(const float4*)&As[kk][ty * 4];
            ulonglong2 b = *(const ulonglong2*)&Bs[kk][tx * 4];
            unsigned long long ad[4] = {pack_dup(a.x), pack_dup(a.y),
                                        pack_dup(a.z), pack_dup(a.w)};
#pragma unroll
            for (int i = 0; i < 4; i++) {
                fma_x2(acc[i][0], ad[i], b.x);
                fma_x2(acc[i][1], ad[i], b.y);
            }
        }
    }
#pragma unroll
    for (int i = 0; i < 4; i++) {
        int r = ty * 4 + i;
        float* o = out + (size_t)(row0 + r) * H + col0 + tx * 4;
#pragma unroll
        for (int j = 0; j < 2; j++) {
            float2 v = unpack2(acc[i][j]);
            o[j * 2 + 0] = v.x;
            o[j * 2 + 1] = v.y;
        }
    }
}

// ---------------- launch ----------------
extern "C" void kernel_launch(void* const* d_in, const int* in_sizes, int n_in,
                              void* d_out, int out_size) {
    const float* x   = (const float*)d_in[0];
    const float* gw  = (const float*)d_in[1];
    const float* wg  = (const float*)d_in[2];
    const float* wu  = (const float*)d_in[3];
    const float* wd  = (const float*)d_in[4];
    const float* swg = (const float*)d_in[5];
    const float* swu = (const float*)d_in[6];
    const float* swd = (const float*)d_in[7];
    float* out = (float*)d_out;

    k_init<<<1, 32>>>();
    k_gate<<<T / 8, 256>>>(x, gw);
    k_scan<<<1, 32>>>();
    k_scatter<<<(T + 255) / 256, 256>>>();

    // shared expert first: its down-proj initializes `out` with plain stores
    k_shared_upgate<<<dim3(FS / TN, T / TM), 256>>>(x, swg, swu);
    k_shared_down<<<dim3(H / TN, T / TM), 256>>>(swd, out);

    // routed experts accumulate on top via atomicAdd
    k_routed_upgate<<<dim3(F / TN, CAPTILES), 256>>>(x, wg, wu);
    k_routed_down<<<dim3(H / TN, CAPTILES), 256>>>(wd, out);
}

// round 3
// speedup vs baseline: 1.0008x; 1.0008x over previous
#include <cuda_runtime.h>

// Problem constants
#define T   2048
#define H   2048
#define NE  8
#define F   1408
#define FS  2816

// GEMM tiling
#define TM  64
#define TN  64
#define TKK 16
#define CAPTILES 72            // 4096/64 row tiles + 8 alignment pads
#define CAP (CAPTILES * TM)    // 4608 bucket slots

// ---------------- device scratch (no allocations allowed) ----------------
__device__ int   g_cnt[NE];
__device__ int   g_fill[NE];
__device__ int   g_seg[NE];
__device__ int   g_tidx[T * 2];
__device__ float g_tw[T * 2];
__device__ int   g_btok[CAP];
__device__ float g_bw[CAP];
__device__ float g_h1[(size_t)CAP * F];     // routed intermediate  (~26 MB)
__device__ float g_h1s[(size_t)T * FS];     // shared intermediate  (~23 MB)

// ---------------- f32x2 packed-FMA helpers (sm_103a FFMA2) ----------------
__device__ __forceinline__ unsigned long long pack_dup(float a) {
    unsigned long long r;
    asm("mov.b64 %0, {%1, %1};" : "=l"(r) : "f"(a));
    return r;
}
__device__ __forceinline__ void fma_x2(unsigned long long& acc,
                                       unsigned long long a,
                                       unsigned long long b) {
    asm("fma.rn.f32x2 %0, %1, %2, %0;" : "+l"(acc) : "l"(a), "l"(b));
}
__device__ __forceinline__ float2 unpack2(unsigned long long v) {
    float2 f;
    asm("mov.b64 {%0, %1}, %2;" : "=f"(f.x), "=f"(f.y) : "l"(v));
    return f;
}

// ---------------- small kernels ----------------
__global__ void k_init() {
    int i = threadIdx.x;
    if (i < NE) { g_cnt[i] = 0; g_fill[i] = 0; }
}

// one warp per token: logits over 8 experts, softmax, top-2, normalize
__global__ void k_gate(const float* __restrict__ x, const float* __restrict__ gw) {
    int gt   = blockIdx.x * blockDim.x + threadIdx.x;
    int t    = gt >> 5;
    int lane = gt & 31;
    if (t >= T) return;
    const float* xr = x + (size_t)t * H;
    float acc[NE];
#pragma unroll
    for (int e = 0; e < NE; e++) acc[e] = 0.f;
    for (int i = lane; i < H; i += 32) {
        float xv = xr[i];
#pragma unroll
        for (int e = 0; e < NE; e++) acc[e] += xv * gw[e * H + i];
    }
#pragma unroll
    for (int e = 0; e < NE; e++) {
#pragma unroll
        for (int o = 16; o > 0; o >>= 1)
            acc[e] += __shfl_down_sync(0xffffffffu, acc[e], o);
    }
    if (lane == 0) {
        float m = acc[0];
#pragma unroll
        for (int e = 1; e < NE; e++) m = fmaxf(m, acc[e]);
        float p[NE], s = 0.f;
#pragma unroll
        for (int e = 0; e < NE; e++) { p[e] = expf(acc[e] - m); s += p[e]; }
        float inv = 1.f / s;
#pragma unroll
        for (int e = 0; e < NE; e++) p[e] *= inv;
        int i0 = 0; float v0 = p[0];
#pragma unroll
        for (int e = 1; e < NE; e++) if (p[e] > v0) { v0 = p[e]; i0 = e; }
        int i1 = -1; float v1 = -1.f;
#pragma unroll
        for (int e = 0; e < NE; e++) if (e != i0 && p[e] > v1) { v1 = p[e]; i1 = e; }
        float d = 1.f / (v0 + v1 + 1e-20f);
        g_tidx[t * 2 + 0] = i0; g_tw[t * 2 + 0] = v0 * d;
        g_tidx[t * 2 + 1] = i1; g_tw[t * 2 + 1] = v1 * d;
        atomicAdd(&g_cnt[i0], 1);
        atomicAdd(&g_cnt[i1], 1);
    }
}

__global__ void k_scan() {
    if (threadIdx.x == 0) {
        int acc = 0;
        for (int e = 0; e < NE; e++) {
            g_seg[e] = acc;
            acc += (g_cnt[e] + TM - 1) / TM * TM;
        }
    }
}

__global__ void k_scatter() {
    int t = blockIdx.x * blockDim.x + threadIdx.x;
    if (t >= T) return;
#pragma unroll
    for (int k = 0; k < 2; k++) {
        int e   = g_tidx[t * 2 + k];
        float w = g_tw[t * 2 + k];
        int pos = atomicAdd(&g_fill[e], 1);
        int slot = g_seg[e] + pos;
        g_btok[slot] = t;
        g_bw[slot]   = w;
    }
}

// ---------------- expert lookup for a routed row tile ----------------
__device__ __forceinline__ void find_expert(int row0, int& e_out, int& valid_out) {
    int e = -1, vr = 0;
    for (int i = 0; i < NE; i++) {
        int st = g_seg[i];
        int sz = (g_cnt[i] + TM - 1) / TM * TM;
        if (row0 >= st && row0 < st + sz) { e = i; vr = g_cnt[i] - (row0 - st); break; }
    }
    e_out = e; valid_out = vr;
}

// ================= GEMM 1: routed gate+up, fused SiLU =================
// h1[slot, F] = silu(x[tok] @ wg_e^T) * (x[tok] @ wu_e^T)
__global__ __launch_bounds__(256) void k_routed_upgate(
    const float* __restrict__ x, const float* __restrict__ wg,
    const float* __restrict__ wu) {
    __shared__ float As[TKK][TM];
    __shared__ float B0[TKK][TN];
    __shared__ float B1[TKK][TN];
    __shared__ int   stok[TM];
    __shared__ int   sh_e, sh_valid;

    int tid  = threadIdx.x;
    int row0 = blockIdx.y * TM;
    if (tid == 0) find_expert(row0, sh_e, sh_valid);
    __syncthreads();
    int e = sh_e;
    if (e < 0 || sh_valid <= 0) return;
    int nvalid = sh_valid > TM ? TM : sh_valid;
    if (tid < TM) stok[tid] = (tid < nvalid) ? g_btok[row0 + tid] : 0;
    __syncthreads();

    int lr = tid >> 2, lq = tid & 3;
    int tx = tid & 15, ty = tid >> 4;
    int col0 = blockIdx.x * TN;
    int atok = stok[lr];
    const float* ap  = x  + (size_t)atok * H + lq * 4;
    const float* bgp = wg + (size_t)e * F * H + (size_t)(col0 + lr) * H + lq * 4;
    const float* bup = wu + (size_t)e * F * H + (size_t)(col0 + lr) * H + lq * 4;

    unsigned long long accg[4][2], accu[4][2];
#pragma unroll
    for (int i = 0; i < 4; i++)
#pragma unroll
        for (int j = 0; j < 2; j++) { accg[i][j] = 0ull; accu[i][j] = 0ull; }

    for (int k0 = 0; k0 < H; k0 += TKK) {
        float4 av = *(const float4*)(ap + k0);
        float4 bg = *(const float4*)(bgp + k0);
        float4 bu = *(const float4*)(bup + k0);
        __syncthreads();
        As[lq * 4 + 0][lr] = av.x; As[lq * 4 + 1][lr] = av.y;
        As[lq * 4 + 2][lr] = av.z; As[lq * 4 + 3][lr] = av.w;
        B0[lq * 4 + 0][lr] = bg.x; B0[lq * 4 + 1][lr] = bg.y;
        B0[lq * 4 + 2][lr] = bg.z; B0[lq * 4 + 3][lr] = bg.w;
        B1[lq * 4 + 0][lr] = bu.x; B1[lq * 4 + 1][lr] = bu.y;
        B1[lq * 4 + 2][lr] = bu.z; B1[lq * 4 + 3][lr] = bu.w;
        __syncthreads();
#pragma unroll
        for (int kk = 0; kk < TKK; kk++) {
            float4 a = *(const float4*)&As[kk][ty * 4];
            ulonglong2 b0 = *(const ulonglong2*)&B0[kk][tx * 4];
            ulonglong2 b1 = *(const ulonglong2*)&B1[kk][tx * 4];
            unsigned long long ad[4] = {pack_dup(a.x), pack_dup(a.y),
                                        pack_dup(a.z), pack_dup(a.w)};
#pragma unroll
            for (int i = 0; i < 4; i++) {
                fma_x2(accg[i][0], ad[i], b0.x);
                fma_x2(accg[i][1], ad[i], b0.y);
                fma_x2(accu[i][0], ad[i], b1.x);
                fma_x2(accu[i][1], ad[i], b1.y);
            }
        }
    }
#pragma unroll
    for (int i = 0; i < 4; i++) {
        int r = ty * 4 + i;
        if (r < nvalid) {
            float* dst = g_h1 + (size_t)(row0 + r) * F + col0 + tx * 4;
#pragma unroll
            for (int j = 0; j < 2; j++) {
                float2 g = unpack2(accg[i][j]);
                float2 u = unpack2(accu[i][j]);
                dst[j * 2 + 0] = g.x * (1.f / (1.f + expf(-g.x))) * u.x;
                dst[j * 2 + 1] = g.y * (1.f / (1.f + expf(-g.y))) * u.y;
            }
        }
    }
}

// ================= GEMM 2: routed down, weighted atomic accumulate =================
__global__ __launch_bounds__(256) void k_routed_down(
    const float* __restrict__ wd, float* __restrict__ out) {
    __shared__ float As[TKK][TM];
    __shared__ float Bs[TKK][TN];
    __shared__ int   stok[TM];
    __shared__ float swt[TM];
    __shared__ int   sh_e, sh_valid;

    int tid  = threadIdx.x;
    int row0 = blockIdx.y * TM;
    if (tid == 0) find_expert(row0, sh_e, sh_valid);
    __syncthreads();
    int e = sh_e;
    if (e < 0 || sh_valid <= 0) return;
    int nvalid = sh_valid > TM ? TM : sh_valid;
    if (tid < TM) {
        bool v = tid < nvalid;
        stok[tid] = v ? g_btok[row0 + tid] : 0;
        swt[tid]  = v ? g_bw[row0 + tid]  : 0.f;
    }
    __syncthreads();

    int lr = tid >> 2, lq = tid & 3;
    int tx = tid & 15, ty = tid >> 4;
    int col0 = blockIdx.x * TN;
    const float* ap = g_h1 + (size_t)(row0 + lr) * F + lq * 4;
    const float* bp = wd + (size_t)e * H * F + (size_t)(col0 + lr) * F + lq * 4;

    unsigned long long acc[4][2];
#pragma unroll
    for (int i = 0; i < 4; i++) { acc[i][0] = 0ull; acc[i][1] = 0ull; }

    for (int k0 = 0; k0 < F; k0 += TKK) {
        float4 av = *(const float4*)(ap + k0);
        float4 bv = *(const float4*)(bp + k0);
        __syncthreads();
        As[lq * 4 + 0][lr] = av.x; As[lq * 4 + 1][lr] = av.y;
        As[lq * 4 + 2][lr] = av.z; As[lq * 4 + 3][lr] = av.w;
        Bs[lq * 4 + 0][lr] = bv.x; Bs[lq * 4 + 1][lr] = bv.y;
        Bs[lq * 4 + 2][lr] = bv.z; Bs[lq * 4 + 3][lr] = bv.w;
        __syncthreads();
#pragma unroll
        for (int kk = 0; kk < TKK; kk++) {
            float4 a = *(const float4*)&As[kk][ty * 4];
            ulonglong2 b = *(const ulonglong2*)&Bs[kk][tx * 4];
            unsigned long long ad[4] = {pack_dup(a.x), pack_dup(a.y),
                                        pack_dup(a.z), pack_dup(a.w)};
#pragma unroll
            for (int i = 0; i < 4; i++) {
                fma_x2(acc[i][0], ad[i], b.x);
                fma_x2(acc[i][1], ad[i], b.y);
            }
        }
    }
#pragma unroll
    for (int i = 0; i < 4; i++) {
        int r = ty * 4 + i;
        if (r < nvalid) {
            int tkn = stok[r];
            float w = swt[r];
            float* o = out + (size_t)tkn * H + col0 + tx * 4;
#pragma unroll
            for (int j = 0; j < 2; j++) {
                float2 v = unpack2(acc[i][j]);
                atomicAdd(&o[j * 2 + 0], w * v.x);
                atomicAdd(&o[j * 2 + 1], w * v.y);
            }
        }
    }
}

// ================= GEMM 3: shared gate+up, fused SiLU =================
__global__ __launch_bounds__(256) void k_shared_upgate(
    const float* __restrict__ x, const float* __restrict__ swg,
    const float* __restrict__ swu) {
    __shared__ float As[TKK][TM];
    __shared__ float B0[TKK][TN];
    __shared__ float B1[TKK][TN];

    int tid = threadIdx.x;
    int row0 = blockIdx.y * TM;
    int col0 = blockIdx.x * TN;
    int lr = tid >> 2, lq = tid & 3;
    int tx = tid & 15, ty = tid >> 4;
    const float* ap  = x   + (size_t)(row0 + lr) * H + lq * 4;
    const float* bgp = swg + (size_t)(col0 + lr) * H + lq * 4;
    const float* bup = swu + (size_t)(col0 + lr) * H + lq * 4;

    unsigned long long accg[4][2], accu[4][2];
#pragma unroll
    for (int i = 0; i < 4; i++)
#pragma unroll
        for (int j = 0; j < 2; j++) { accg[i][j] = 0ull; accu[i][j] = 0ull; }

    for (int k0 = 0; k0 < H; k0 += TKK) {
        float4 av = *(const float4*)(ap + k0);
        float4 bg = *(const float4*)(bgp + k0);
        float4 bu = *(const float4*)(bup + k0);
        __syncthreads();
        As[lq * 4 + 0][lr] = av.x; As[lq * 4 + 1][lr] = av.y;
        As[lq * 4 + 2][lr] = av.z; As[lq * 4 + 3][lr] = av.w;
        B0[lq * 4 + 0][lr] = bg.x; B0[lq * 4 + 1][lr] = bg.y;
        B0[lq * 4 + 2][lr] = bg.z; B0[lq * 4 + 3][lr] = bg.w;
        B1[lq * 4 + 0][lr] = bu.x; B1[lq * 4 + 1][lr] = bu.y;
        B1[lq * 4 + 2][lr] = bu.z; B1[lq * 4 + 3][lr] = bu.w;
        __syncthreads();
#pragma unroll
        for (int kk = 0; kk < TKK; kk++) {
            float4 a = *(const float4*)&As[kk][ty * 4];
            ulonglong2 b0 = *(const ulonglong2*)&B0[kk][tx * 4];
            ulonglong2 b1 = *(const ulonglong2*)&B1[kk][tx * 4];
            unsigned long long ad[4] = {pack_dup(a.x), pack_dup(a.y),
                                        pack_dup(a.z), pack_dup(a.w)};
#pragma unroll
            for (int i = 0; i < 4; i++) {
                fma_x2(accg[i][0], ad[i], b0.x);
                fma_x2(accg[i][1], ad[i], b0.y);
                fma_x2(accu[i][0], ad[i], b1.x);
                fma_x2(accu[i][1], ad[i], b1.y);
            }
        }
    }
#pragma unroll
    for (int i = 0; i < 4; i++) {
        int r = ty * 4 + i;
        float* dst = g_h1s + (size_t)(row0 + r) * FS + col0 + tx * 4;
#pragma unroll
        for (int j = 0; j < 2; j++) {
            float2 g = unpack2(accg[i][j]);
            float2 u = unpack2(accu[i][j]);
            dst[j * 2 + 0] = g.x * (1.f / (1.f + expf(-g.x))) * u.x;
            dst[j * 2 + 1] = g.y * (1.f / (1.f + expf(-g.y))) * u.y;
        }
    }
}

// ================= GEMM 4: shared down, plain store (initializes out) =================
__global__ __launch_bounds__(256) void k_shared_down(
    const float* __restrict__ swd, float* __restrict__ out) {
    __shared__ float As[TKK][TM];
    __shared__ float Bs[TKK][TN];

    int tid = threadIdx.x;
    int row0 = blockIdx.y * TM;
    int col0 = blockIdx.x * TN;
    int lr = tid >> 2, lq = tid & 3;
    int tx = tid & 15, ty = tid >> 4;
    const float* ap = g_h1s + (size_t)(row0 + lr) * FS + lq * 4;
    const float* bp = swd   + (size_t)(col0 + lr) * FS + lq * 4;

    unsigned long long acc[4][2];
#pragma unroll
    for (int i = 0; i < 4; i++) { acc[i][0] = 0ull; acc[i][1] = 0ull; }

    for (int k0 = 0; k0 < FS; k0 += TKK) {
        float4 av = *(const float4*)(ap + k0);
        float4 bv = *(const float4*)(bp + k0);
        __syncthreads();
        As[lq * 4 + 0][lr] = av.x; As[lq * 4 + 1][lr] = av.y;
        As[lq * 4 + 2][lr] = av.z; As[lq * 4 + 3][lr] = av.w;
        Bs[lq * 4 + 0][lr] = bv.x; Bs[lq * 4 + 1][lr] = bv.y;
        Bs[lq * 4 + 2][lr] = bv.z; Bs[lq * 4 + 3][lr] = bv.w;
        __syncthreads();
#pragma unroll
        for (int kk = 0; kk < TKK; kk++) {
            float4 a = *(const float4*)&As[kk][ty * 4];
            ulonglong2 b = *(const ulonglong2*)&Bs[kk][tx * 4];
            unsigned long long ad[4] = {pack_dup(a.x), pack_dup(a.y),
                                        pack_dup(a.z), pack_dup(a.w)};
#pragma unroll
            for (int i = 0; i < 4; i++) {
                fma_x2(acc[i][0], ad[i], b.x);
                fma_x2(acc[i][1], ad[i], b.y);
            }
        }
    }
#pragma unroll
    for (int i = 0; i < 4; i++) {
        int r = ty * 4 + i;
        float* o = out + (size_t)(row0 + r) * H + col0 + tx * 4;
#pragma unroll
        for (int j = 0; j < 2; j++) {
            float2 v = unpack2(acc[i][j]);
            o[j * 2 + 0] = v.x;
            o[j * 2 + 1] = v.y;
        }
    }
}

// ---------------- launch ----------------
extern "C" void kernel_launch(void* const* d_in, const int* in_sizes, int n_in,
                              void* d_out, int out_size) {
    const float* x   = (const float*)d_in[0];
    const float* gw  = (const float*)d_in[1];
    const float* wg  = (const float*)d_in[2];
    const float* wu  = (const float*)d_in[3];
    const float* wd  = (const float*)d_in[4];
    const float* swg = (const float*)d_in[5];
    const float* swu = (const float*)d_in[6];
    const float* swd = (const float*)d_in[7];
    float* out = (float*)d_out;

    k_init<<<1, 32>>>();
    k_gate<<<T / 8, 256>>>(x, gw);
    k_scan<<<1, 32>>>();
    k_scatter<<<(T + 255) / 256, 256>>>();

    // shared expert first: its down-proj initializes `out` with plain stores
    k_shared_upgate<<<dim3(FS / TN, T / TM), 256>>>(x, swg, swu);
    k_shared_down<<<dim3(H / TN, T / TM), 256>>>(swd, out);

    // routed experts accumulate on top via atomicAdd
    k_routed_upgate<<<dim3(F / TN, CAPTILES), 256>>>(x, wg, wu);
    k_routed_down<<<dim3(H / TN, CAPTILES), 256>>>(wd, out);
}

// round 5
// speedup vs baseline: 1.9882x; 1.9867x over previous
#include <cuda_runtime.h>
#include <cstdint>

// ---------------- problem constants ----------------
#define NT   2048      // tokens
#define HD   2048      // hidden
#define NE   8         // experts
#define FF   1408      // routed intermediate
#define FSS  2816      // shared intermediate
#define TMR  128       // M tile
#define CAPTILES 40
#define CAP (CAPTILES * TMR)

// ---------------- device scratch ----------------
__device__ int   g_cnt[NE];
__device__ int   g_fill[NE];
__device__ int   g_seg[NE];
__device__ int   g_tidx[NT * 2];
__device__ float g_tw[NT * 2];
__device__ int   g_btok[CAP];
__device__ float g_bw[CAP];
__device__ float g_h1[(size_t)CAP * FF];
__device__ float g_h1s[(size_t)NT * FSS];

// ---------------- helpers ----------------
__device__ __forceinline__ uint32_t smem_u32(const void* p) {
    uint32_t a;
    asm("{ .reg .u64 t; cvta.to.shared.u64 t, %1; cvt.u32.u64 %0, t; }" : "=r"(a) : "l"(p));
    return a;
}

__device__ __forceinline__ void ldsm4(uint32_t* r, uint32_t addr) {
    asm volatile("ldmatrix.sync.aligned.m8n8.x4.shared.b16 {%0,%1,%2,%3}, [%4];"
        : "=r"(r[0]), "=r"(r[1]), "=r"(r[2]), "=r"(r[3]) : "r"(addr));
}

__device__ __forceinline__ void mma16816(float* c, const uint32_t* a, const uint32_t* b) {
    asm volatile(
        "mma.sync.aligned.m16n8k16.row.col.f32.bf16.bf16.f32 "
        "{%0,%1,%2,%3}, {%4,%5,%6,%7}, {%8,%9}, {%0,%1,%2,%3};"
        : "+f"(c[0]), "+f"(c[1]), "+f"(c[2]), "+f"(c[3])
        : "r"(a[0]), "r"(a[1]), "r"(a[2]), "r"(a[3]), "r"(b[0]), "r"(b[1]));
}

// convert 8 fp32 -> bf16 hi/lo, store one v4 (16B) to each swizzled plane
__device__ __forceinline__ void cvt8_store(uint32_t hip, uint32_t lop, uint32_t off,
                                           float4 a, float4 b) {
    uint32_t h0, h1, h2, h3, l0, l1, l2, l3;
    asm("cvt.rn.bf16x2.f32 %0, %1, %2;" : "=r"(h0) : "f"(a.y), "f"(a.x));
    asm("cvt.rn.bf16x2.f32 %0, %1, %2;" : "=r"(h1) : "f"(a.w), "f"(a.z));
    asm("cvt.rn.bf16x2.f32 %0, %1, %2;" : "=r"(h2) : "f"(b.y), "f"(b.x));
    asm("cvt.rn.bf16x2.f32 %0, %1, %2;" : "=r"(h3) : "f"(b.w), "f"(b.z));
    float r0 = a.x - __uint_as_float(h0 << 16);
    float r1 = a.y - __uint_as_float(h0 & 0xffff0000u);
    float r2 = a.z - __uint_as_float(h1 << 16);
    float r3 = a.w - __uint_as_float(h1 & 0xffff0000u);
    float r4 = b.x - __uint_as_float(h2 << 16);
    float r5 = b.y - __uint_as_float(h2 & 0xffff0000u);
    float r6 = b.z - __uint_as_float(h3 << 16);
    float r7 = b.w - __uint_as_float(h3 & 0xffff0000u);
    asm("cvt.rn.bf16x2.f32 %0, %1, %2;" : "=r"(l0) : "f"(r1), "f"(r0));
    asm("cvt.rn.bf16x2.f32 %0, %1, %2;" : "=r"(l1) : "f"(r3), "f"(r2));
    asm("cvt.rn.bf16x2.f32 %0, %1, %2;" : "=r"(l2) : "f"(r5), "f"(r4));
    asm("cvt.rn.bf16x2.f32 %0, %1, %2;" : "=r"(l3) : "f"(r7), "f"(r6));
    uint32_t ah = hip + off; ah ^= ((ah >> 3) & 0x70u);
    uint32_t al = lop + off; al ^= ((al >> 3) & 0x70u);
    asm volatile("st.shared.v4.b32 [%0], {%1,%2,%3,%4};" :: "r"(ah), "r"(h0), "r"(h1), "r"(h2), "r"(h3) : "memory");
    asm volatile("st.shared.v4.b32 [%0], {%1,%2,%3,%4};" :: "r"(al), "r"(l0), "r"(l1), "r"(l2), "r"(l3) : "memory");
}

// this thread fills 32 consecutive K fp32 of its row into swizzled hi/lo bf16 planes
__device__ __forceinline__ void fill_plane(const float* __restrict__ src,
                                           uint32_t hip, uint32_t lop, uint32_t boff) {
#pragma unroll
    for (int j = 0; j < 4; j++) {
        float4 a = *(const float4*)(src + j * 8);
        float4 b = *(const float4*)(src + j * 8 + 4);
        cvt8_store(hip, lop, boff + j * 16, a, b);
    }
}

// ---------------- gating ----------------
__global__ void k_init() {
    int i = threadIdx.x;
    if (i < NE) { g_cnt[i] = 0; g_fill[i] = 0; }
}

__global__ void k_gate(const float* __restrict__ x, const float* __restrict__ gw) {
    int gt = blockIdx.x * blockDim.x + threadIdx.x;
    int t = gt >> 5, lane = gt & 31;
    if (t >= NT) return;
    const float* xr = x + (size_t)t * HD;
    float acc[NE];
#pragma unroll
    for (int e = 0; e < NE; e++) acc[e] = 0.f;
    for (int i = lane; i < HD; i += 32) {
        float xv = xr[i];
#pragma unroll
        for (int e = 0; e < NE; e++) acc[e] += xv * gw[e * HD + i];
    }
#pragma unroll
    for (int e = 0; e < NE; e++)
#pragma unroll
        for (int o = 16; o > 0; o >>= 1)
            acc[e] += __shfl_down_sync(0xffffffffu, acc[e], o);
    if (lane == 0) {
        float m = acc[0];
#pragma unroll
        for (int e = 1; e < NE; e++) m = fmaxf(m, acc[e]);
        float p[NE], s = 0.f;
#pragma unroll
        for (int e = 0; e < NE; e++) { p[e] = expf(acc[e] - m); s += p[e]; }
        float inv = 1.f / s;
#pragma unroll
        for (int e = 0; e < NE; e++) p[e] *= inv;
        int i0 = 0; float v0 = p[0];
#pragma unroll
        for (int e = 1; e < NE; e++) if (p[e] > v0) { v0 = p[e]; i0 = e; }
        int i1 = -1; float v1 = -1.f;
#pragma unroll
        for (int e = 0; e < NE; e++) if (e != i0 && p[e] > v1) { v1 = p[e]; i1 = e; }
        float d = 1.f / (v0 + v1 + 1e-20f);
        g_tidx[t * 2 + 0] = i0; g_tw[t * 2 + 0] = v0 * d;
        g_tidx[t * 2 + 1] = i1; g_tw[t * 2 + 1] = v1 * d;
        atomicAdd(&g_cnt[i0], 1);
        atomicAdd(&g_cnt[i1], 1);
    }
}

__global__ void k_scan() {
    if (threadIdx.x == 0) {
        int acc = 0;
        for (int e = 0; e < NE; e++) {
            g_seg[e] = acc;
            acc += (g_cnt[e] + TMR - 1) / TMR * TMR;
        }
    }
}

__global__ void k_scatter() {
    int t = blockIdx.x * blockDim.x + threadIdx.x;
    if (t >= NT) return;
#pragma unroll
    for (int k = 0; k < 2; k++) {
        int e = g_tidx[t * 2 + k];
        float w = g_tw[t * 2 + k];
        int pos = atomicAdd(&g_fill[e], 1);
        g_btok[g_seg[e] + pos] = t;
        g_bw[g_seg[e] + pos] = w;
    }
}

__device__ __forceinline__ void find_expert(int row0, int& e_out, int& valid_out) {
    int e = -1, vr = 0;
    for (int i = 0; i < NE; i++) {
        int st = g_seg[i];
        int sz = (g_cnt[i] + TMR - 1) / TMR * TMR;
        if (row0 >= st && row0 < st + sz) { e = i; vr = g_cnt[i] - (row0 - st); break; }
    }
    e_out = e; valid_out = vr;
}

// ================= fused gate+up GEMM =================
// per buffer: Ah, Al, Gh, Gl, Uh, Ul planes (16KB each, SW128) = 96KB; double buffered
#define UP_BUFSTRIDE 98304u
#define UP_BUFS     196608u
#define UP_SMEM (UP_BUFS + 2048)

template <int ROUTED>
__global__ __launch_bounds__(256, 1)
void k_upgate(const float* __restrict__ x,
              const float* __restrict__ wg_all,
              const float* __restrict__ wu_all) {
    extern __shared__ char smem[];
    uint32_t sb0 = smem_u32(smem);
    uint32_t sb = (sb0 + 1023u) & ~1023u;
    char* ctrlp = smem + (sb - sb0) + UP_BUFS;
    int* sh_meta = (int*)ctrlp;
    int* stok = (int*)(ctrlp + 16);

    int tid = threadIdx.x;
    int lane = tid & 31, wid = tid >> 5;
    int wm = wid & 1, wn = wid >> 1;
    int row0 = blockIdx.y * TMR;
    int col0 = blockIdx.x * TMR;

    int e = 0, nvalid = TMR;
    if (ROUTED) {
        if (tid == 0) {
            int ee, vv; find_expert(row0, ee, vv);
            sh_meta[0] = ee; sh_meta[1] = vv;
        }
        __syncthreads();
        e = sh_meta[0];
        int v = sh_meta[1];
        if (e < 0 || v <= 0) return;
        nvalid = v > TMR ? TMR : v;
        if (tid < TMR) stok[tid] = (tid < nvalid) ? g_btok[row0 + tid] : 0;
        __syncthreads();
    }

    // fill mapping: each thread owns (row = tid>>1, khalf = tid&1) -> 32 fp32
    int frow = tid >> 1, fhf = tid & 1;
    const float* ap;
    if (ROUTED) ap = x + (size_t)stok[frow] * HD + fhf * 32;
    else        ap = x + (size_t)(row0 + frow) * HD + fhf * 32;
    const float* bgp = (ROUTED ? wg_all + (size_t)e * FF * HD : wg_all)
                       + (size_t)(col0 + frow) * HD + fhf * 32;
    const float* bup = (ROUTED ? wu_all + (size_t)e * FF * HD : wu_all)
                       + (size_t)(col0 + frow) * HD + fhf * 32;
    uint32_t boff = frow * 128 + fhf * 64;

    // ldmatrix addressing constants
    uint32_t xorv  = (lane & 7) << 4;
    uint32_t a_row = (uint32_t)(wm * 64 + (lane & 15)) * 128;
    uint32_t a_ksel = (uint32_t)(lane >> 4) * 16;
    uint32_t b_row = (uint32_t)(wn * 32 + ((lane >> 4) * 8) + (lane & 7)) * 128;
    uint32_t b_ksel = (uint32_t)((lane >> 3) & 1) * 16;

    float accg[4][4][4], accu[4][4][4];
#pragma unroll
    for (int i = 0; i < 4; i++)
#pragma unroll
        for (int j = 0; j < 4; j++)
#pragma unroll
            for (int q = 0; q < 4; q++) { accg[i][j][q] = 0.f; accu[i][j][q] = 0.f; }

    const int NC = HD / 64;
    // prologue fill chunk 0
    {
        uint32_t pb = sb;
        fill_plane(ap,  pb + 0,      pb + 16384u, boff);
        fill_plane(bgp, pb + 32768u, pb + 49152u, boff);
        fill_plane(bup, pb + 65536u, pb + 81920u, boff);
    }
    __syncthreads();

    for (int c = 0; c < NC; c++) {
        uint32_t pb = sb + (uint32_t)(c & 1) * UP_BUFSTRIDE;
#pragma unroll
        for (int s = 0; s < 4; s++) {
            uint32_t koa = (uint32_t)(s * 32 + a_ksel) ^ xorv;
            uint32_t kob = (uint32_t)(s * 32 + b_ksel) ^ xorv;
            uint32_t ah[4][4], al[4][4];
#pragma unroll
            for (int i = 0; i < 4; i++) {
                uint32_t off = a_row + (uint32_t)i * 2048 + koa;
                ldsm4(ah[i], pb + off);            // Ah plane
                ldsm4(al[i], pb + 16384u + off);   // Al plane
            }
            uint32_t bh[2][4], bl[2][4];
#pragma unroll
            for (int jj = 0; jj < 2; jj++) {
                uint32_t off = b_row + (uint32_t)jj * 2048 + kob;
                ldsm4(bh[jj], pb + 32768u + off);  // Gh
                ldsm4(bl[jj], pb + 49152u + off);  // Gl
            }
#pragma unroll
            for (int i = 0; i < 4; i++)
#pragma unroll
                for (int j = 0; j < 4; j++) {
                    const uint32_t* fh = &bh[j >> 1][(j & 1) * 2];
                    const uint32_t* fl = &bl[j >> 1][(j & 1) * 2];
                    mma16816(accg[i][j], ah[i], fh);
                    mma16816(accg[i][j], al[i], fh);
                    mma16816(accg[i][j], ah[i], fl);
                }
#pragma unroll
            for (int jj = 0; jj < 2; jj++) {
                uint32_t off = b_row + (uint32_t)jj * 2048 + kob;
                ldsm4(bh[jj], pb + 65536u + off);  // Uh
                ldsm4(bl[jj], pb + 81920u + off);  // Ul
            }
#pragma unroll
            for (int i = 0; i < 4; i++)
#pragma unroll
                for (int j = 0; j < 4; j++) {
                    const uint32_t* fh = &bh[j >> 1][(j & 1) * 2];
                    const uint32_t* fl = &bl[j >> 1][(j & 1) * 2];
                    mma16816(accu[i][j], ah[i], fh);
                    mma16816(accu[i][j], al[i], fh);
                    mma16816(accu[i][j], ah[i], fl);
                }
        }
        if (c + 1 < NC) {
            uint32_t pn = sb + (uint32_t)((c + 1) & 1) * UP_BUFSTRIDE;
            int k0 = (c + 1) * 64;
            fill_plane(ap + k0,  pn + 0,      pn + 16384u, boff);
            fill_plane(bgp + k0, pn + 32768u, pn + 49152u, boff);
            fill_plane(bup + k0, pn + 65536u, pn + 81920u, boff);
        }
        __syncthreads();
    }

    // epilogue: SiLU(g) * u -> h1
    const int LDC = ROUTED ? FF : FSS;
    float* dst0 = ROUTED ? g_h1 : g_h1s;
#pragma unroll
    for (int i = 0; i < 4; i++) {
        int rl0 = wm * 64 + i * 16 + (lane >> 2);
        int rl1 = rl0 + 8;
#pragma unroll
        for (int j = 0; j < 4; j++) {
            int cl = wn * 32 + j * 8 + (lane & 3) * 2;
            float* dr0 = dst0 + (size_t)(row0 + rl0) * LDC + col0 + cl;
            float* dr1 = dst0 + (size_t)(row0 + rl1) * LDC + col0 + cl;
            if (!ROUTED || rl0 < nvalid) {
                float g0 = accg[i][j][0], g1 = accg[i][j][1];
                float u0 = accu[i][j][0], u1 = accu[i][j][1];
                float2 o;
                o.x = g0 / (1.f + __expf(-g0)) * u0;
                o.y = g1 / (1.f + __expf(-g1)) * u1;
                *(float2*)dr0 = o;
            }
            if (!ROUTED || rl1 < nvalid) {
                float g0 = accg[i][j][2], g1 = accg[i][j][3];
                float u0 = accu[i][j][2], u1 = accu[i][j][3];
                float2 o;
                o.x = g0 / (1.f + __expf(-g0)) * u0;
                o.y = g1 / (1.f + __expf(-g1)) * u1;
                *(float2*)dr1 = o;
            }
        }
    }
}

// ================= down GEMM =================
// per buffer: Ah, Al, Bh, Bl planes = 64KB; double buffered
#define DN_BUFSTRIDE 65536u
#define DN_BUFS     131072u
#define DN_SMEM (DN_BUFS + 2048)

template <int ROUTED>
__global__ __launch_bounds__(256, 1)
void k_down(const float* __restrict__ wdall, float* __restrict__ out) {
    extern __shared__ char smem[];
    uint32_t sb0 = smem_u32(smem);
    uint32_t sb = (sb0 + 1023u) & ~1023u;
    char* ctrlp = smem + (sb - sb0) + DN_BUFS;
    int* sh_meta = (int*)ctrlp;
    int* stok = (int*)(ctrlp + 16);
    float* swt = (float*)(ctrlp + 16 + 512);

    int tid = threadIdx.x;
    int lane = tid & 31, wid = tid >> 5;
    int wm = wid & 1, wn = wid >> 1;
    int row0 = blockIdx.y * TMR;
    int col0 = blockIdx.x * TMR;

    int e = 0, nvalid = TMR;
    if (ROUTED) {
        if (tid == 0) {
            int ee, vv; find_expert(row0, ee, vv);
            sh_meta[0] = ee; sh_meta[1] = vv;
        }
        __syncthreads();
        e = sh_meta[0];
        int v = sh_meta[1];
        if (e < 0 || v <= 0) return;
        nvalid = v > TMR ? TMR : v;
        if (tid < TMR) {
            bool ok = tid < nvalid;
            stok[tid] = ok ? g_btok[row0 + tid] : 0;
            swt[tid]  = ok ? g_bw[row0 + tid]   : 0.f;
        }
        __syncthreads();
    }

    const int KD = ROUTED ? FF : FSS;
    int frow = tid >> 1, fhf = tid & 1;
    const float* ap = (ROUTED ? g_h1 + (size_t)(row0 + frow) * FF
                              : g_h1s + (size_t)(row0 + frow) * FSS) + fhf * 32;
    const float* bp = (ROUTED ? wdall + (size_t)e * HD * FF : wdall)
                      + (size_t)(col0 + frow) * KD + fhf * 32;
    uint32_t boff = frow * 128 + fhf * 64;

    uint32_t xorv  = (lane & 7) << 4;
    uint32_t a_row = (uint32_t)(wm * 64 + (lane & 15)) * 128;
    uint32_t a_ksel = (uint32_t)(lane >> 4) * 16;
    uint32_t b_row = (uint32_t)(wn * 32 + ((lane >> 4) * 8) + (lane & 7)) * 128;
    uint32_t b_ksel = (uint32_t)((lane >> 3) & 1) * 16;

    float acc[4][4][4];
#pragma unroll
    for (int i = 0; i < 4; i++)
#pragma unroll
        for (int j = 0; j < 4; j++)
#pragma unroll
            for (int q = 0; q < 4; q++) acc[i][j][q] = 0.f;

    const int NC = KD / 64;
    {
        uint32_t pb = sb;
        fill_plane(ap, pb + 0,      pb + 16384u, boff);
        fill_plane(bp, pb + 32768u, pb + 49152u, boff);
    }
    __syncthreads();

    for (int c = 0; c < NC; c++) {
        uint32_t pb = sb + (uint32_t)(c & 1) * DN_BUFSTRIDE;
#pragma unroll
        for (int s = 0; s < 4; s++) {
            uint32_t koa = (uint32_t)(s * 32 + a_ksel) ^ xorv;
            uint32_t kob = (uint32_t)(s * 32 + b_ksel) ^ xorv;
            uint32_t ah[4][4], al[4][4];
#pragma unroll
            for (int i = 0; i < 4; i++) {
                uint32_t off = a_row + (uint32_t)i * 2048 + koa;
                ldsm4(ah[i], pb + off);
                ldsm4(al[i], pb + 16384u + off);
            }
            uint32_t bh[2][4], bl[2][4];
#pragma unroll
            for (int jj = 0; jj < 2; jj++) {
                uint32_t off = b_row + (uint32_t)jj * 2048 + kob;
                ldsm4(bh[jj], pb + 32768u + off);
                ldsm4(bl[jj], pb + 49152u + off);
            }
#pragma unroll
            for (int i = 0; i < 4; i++)
#pragma unroll
                for (int j = 0; j < 4; j++) {
                    const uint32_t* fh = &bh[j >> 1][(j & 1) * 2];
                    const uint32_t* fl = &bl[j >> 1][(j & 1) * 2];
                    mma16816(acc[i][j], ah[i], fh);
                    mma16816(acc[i][j], al[i], fh);
                    mma16816(acc[i][j], ah[i], fl);
                }
        }
        if (c + 1 < NC) {
            uint32_t pn = sb + (uint32_t)((c + 1) & 1) * DN_BUFSTRIDE;
            int k0 = (c + 1) * 64;
            fill_plane(ap + k0, pn + 0,      pn + 16384u, boff);
            fill_plane(bp + k0, pn + 32768u, pn + 49152u, boff);
        }
        __syncthreads();
    }

    // epilogue
#pragma unroll
    for (int i = 0; i < 4; i++) {
        int rl0 = wm * 64 + i * 16 + (lane >> 2);
        int rl1 = rl0 + 8;
#pragma unroll
        for (int j = 0; j < 4; j++) {
            int cl = wn * 32 + j * 8 + (lane & 3) * 2;
            if (ROUTED) {
                if (rl0 < nvalid) {
                    float w = swt[rl0];
                    float* o = out + (size_t)stok[rl0] * HD + col0 + cl;
                    atomicAdd(&o[0], w * acc[i][j][0]);
                    atomicAdd(&o[1], w * acc[i][j][1]);
                }
                if (rl1 < nvalid) {
                    float w = swt[rl1];
                    float* o = out + (size_t)stok[rl1] * HD + col0 + cl;
                    atomicAdd(&o[0], w * acc[i][j][2]);
                    atomicAdd(&o[1], w * acc[i][j][3]);
                }
            } else {
                float2 v0; v0.x = acc[i][j][0]; v0.y = acc[i][j][1];
                float2 v1; v1.x = acc[i][j][2]; v1.y = acc[i][j][3];
                *(float2*)(out + (size_t)(row0 + rl0) * HD + col0 + cl) = v0;
                *(float2*)(out + (size_t)(row0 + rl1) * HD + col0 + cl) = v1;
            }
        }
    }
}

// ---------------- launch ----------------
extern "C" void kernel_launch(void* const* d_in, const int* in_sizes, int n_in,
                              void* d_out, int out_size) {
    const float* x   = (const float*)d_in[0];
    const float* gw  = (const float*)d_in[1];
    const float* wg  = (const float*)d_in[2];
    const float* wu  = (const float*)d_in[3];
    const float* wd  = (const float*)d_in[4];
    const float* swg = (const float*)d_in[5];
    const float* swu = (const float*)d_in[6];
    const float* swd = (const float*)d_in[7];
    float* out = (float*)d_out;

    cudaFuncSetAttribute(k_upgate<1>, cudaFuncAttributeMaxDynamicSharedMemorySize, UP_SMEM);
    cudaFuncSetAttribute(k_upgate<0>, cudaFuncAttributeMaxDynamicSharedMemorySize, UP_SMEM);
    cudaFuncSetAttribute(k_down<1>,   cudaFuncAttributeMaxDynamicSharedMemorySize, DN_SMEM);
    cudaFuncSetAttribute(k_down<0>,   cudaFuncAttributeMaxDynamicSharedMemorySize, DN_SMEM);

    k_init<<<1, 32>>>();
    k_gate<<<NT / 8, 256>>>(x, gw);
    k_scan<<<1, 32>>>();
    k_scatter<<<(NT + 255) / 256, 256>>>();

    // shared expert first: its down-proj initializes `out` with plain stores
    k_upgate<0><<<dim3(FSS / TMR, NT / TMR), 256, UP_SMEM>>>(x, swg, swu);
    k_down<0><<<dim3(HD / TMR, NT / TMR), 256, DN_SMEM>>>(swd, out);

    // routed experts accumulate on top via atomicAdd
    k_upgate<1><<<dim3(FF / TMR, CAPTILES), 256, UP_SMEM>>>(x, wg, wu);
    k_down<1><<<dim3(HD / TMR, CAPTILES), 256, DN_SMEM>>>(wd, out);
}

// round 7
// speedup vs baseline: 2.2649x; 1.1392x over previous
#include <cuda_runtime.h>
#include <cstdint>

// ---------------- problem constants ----------------
#define NT   2048
#define HD   2048
#define NE   8
#define FF   1408
#define FSS  2816
#define TMR  128
#define CAPTILES 40
#define CAP (CAPTILES * TMR)

#define KCH   32           // K elements per pipeline stage
#define ROWB  80u          // padded smem row bytes (64B data + 16B pad)
#define PL    10240u       // plane bytes = 128 rows * 80B
#define STG_UP (6u * PL)   // 61440
#define STG_DN (4u * PL)   // 40960
#define UP_SMEM (3 * 61440 + 4096)   // 188416: 3 stages + control (528B used)
#define DN_SMEM (3 * 40960 + 4096)   // 126976: 3 stages + control (1040B used)

// ---------------- device scratch ----------------
__device__ int   g_cnt[NE];
__device__ int   g_fill[NE];
__device__ int   g_seg[NE];
__device__ int   g_tidx[NT * 2];
__device__ float g_tw[NT * 2];
__device__ int   g_btok[CAP];
__device__ float g_bw[CAP];

// bf16 hi/lo planes (pre-converted every launch; deterministic)
__device__ uint16_t b_xh[(size_t)NT * HD],   b_xl[(size_t)NT * HD];
__device__ uint16_t b_wgh[(size_t)NE * FF * HD], b_wgl[(size_t)NE * FF * HD];
__device__ uint16_t b_wuh[(size_t)NE * FF * HD], b_wul[(size_t)NE * FF * HD];
__device__ uint16_t b_wdh[(size_t)NE * HD * FF], b_wdl[(size_t)NE * HD * FF];
__device__ uint16_t b_sgh[(size_t)FSS * HD], b_sgl[(size_t)FSS * HD];
__device__ uint16_t b_suh[(size_t)FSS * HD], b_sul[(size_t)FSS * HD];
__device__ uint16_t b_sdh[(size_t)HD * FSS], b_sdl[(size_t)HD * FSS];
__device__ uint16_t b_h1h[(size_t)CAP * FF], b_h1l[(size_t)CAP * FF];
__device__ uint16_t b_h1sh[(size_t)NT * FSS], b_h1sl[(size_t)NT * FSS];

// ---------------- helpers ----------------
__device__ __forceinline__ uint32_t smem_u32(const void* p) {
    uint32_t a;
    asm("{ .reg .u64 t; cvta.to.shared.u64 t, %1; cvt.u32.u64 %0, t; }" : "=r"(a) : "l"(p));
    return a;
}
__device__ __forceinline__ void ldsm4(uint32_t* r, uint32_t addr) {
    asm volatile("ldmatrix.sync.aligned.m8n8.x4.shared.b16 {%0,%1,%2,%3}, [%4];"
        : "=r"(r[0]), "=r"(r[1]), "=r"(r[2]), "=r"(r[3]) : "r"(addr));
}
__device__ __forceinline__ void mma16816(float* c, const uint32_t* a, const uint32_t* b) {
    asm volatile(
        "mma.sync.aligned.m16n8k16.row.col.f32.bf16.bf16.f32 "
        "{%0,%1,%2,%3}, {%4,%5,%6,%7}, {%8,%9}, {%0,%1,%2,%3};"
        : "+f"(c[0]), "+f"(c[1]), "+f"(c[2]), "+f"(c[3])
        : "r"(a[0]), "r"(a[1]), "r"(a[2]), "r"(a[3]), "r"(b[0]), "r"(b[1]));
}
__device__ __forceinline__ void cp2(uint32_t dst, const uint16_t* src) {
    asm volatile(
        "cp.async.cg.shared.global [%0], [%1], 16;\n\t"
        "cp.async.cg.shared.global [%2], [%3], 16;"
        :: "r"(dst), "l"(src), "r"(dst + 16u), "l"(src + 8) : "memory");
}
__device__ __forceinline__ void cp_commit() {
    asm volatile("cp.async.commit_group;" ::: "memory");
}
template <int N> __device__ __forceinline__ void cp_wait() {
    asm volatile("cp.async.wait_group %0;" :: "n"(N) : "memory");
}
// split fp32 pair -> bf16x2 hi + bf16x2 lo, store 4B each
__device__ __forceinline__ void split_store(uint16_t* hi, uint16_t* lo, size_t idx2,
                                            float o0, float o1) {
    uint32_t hp, lp;
    asm("cvt.rn.bf16x2.f32 %0, %1, %2;" : "=r"(hp) : "f"(o1), "f"(o0));
    float r0 = o0 - __uint_as_float(hp << 16);
    float r1 = o1 - __uint_as_float(hp & 0xffff0000u);
    asm("cvt.rn.bf16x2.f32 %0, %1, %2;" : "=r"(lp) : "f"(r1), "f"(r0));
    ((uint32_t*)hi)[idx2] = hp;
    ((uint32_t*)lo)[idx2] = lp;
}

// ---------------- conversion kernel (fp32 -> bf16 hi/lo) ----------------
__global__ void k_cvt(const float* __restrict__ src, int which, int n4) {
    int i = blockIdx.x * blockDim.x + threadIdx.x;
    if (i >= n4) return;
    uint16_t *hi, *lo;
    switch (which) {
        case 0: hi = b_xh;  lo = b_xl;  break;
        case 1: hi = b_wgh; lo = b_wgl; break;
        case 2: hi = b_wuh; lo = b_wul; break;
        case 3: hi = b_wdh; lo = b_wdl; break;
        case 4: hi = b_sgh; lo = b_sgl; break;
        case 5: hi = b_suh; lo = b_sul; break;
        default: hi = b_sdh; lo = b_sdl; break;
    }
    float4 v = ((const float4*)src)[i];
    uint32_t h0, h1, l0, l1;
    asm("cvt.rn.bf16x2.f32 %0, %1, %2;" : "=r"(h0) : "f"(v.y), "f"(v.x));
    asm("cvt.rn.bf16x2.f32 %0, %1, %2;" : "=r"(h1) : "f"(v.w), "f"(v.z));
    float r0 = v.x - __uint_as_float(h0 << 16);
    float r1 = v.y - __uint_as_float(h0 & 0xffff0000u);
    float r2 = v.z - __uint_as_float(h1 << 16);
    float r3 = v.w - __uint_as_float(h1 & 0xffff0000u);
    asm("cvt.rn.bf16x2.f32 %0, %1, %2;" : "=r"(l0) : "f"(r1), "f"(r0));
    asm("cvt.rn.bf16x2.f32 %0, %1, %2;" : "=r"(l1) : "f"(r3), "f"(r2));
    uint2 hv; hv.x = h0; hv.y = h1;
    uint2 lv; lv.x = l0; lv.y = l1;
    ((uint2*)hi)[i] = hv;
    ((uint2*)lo)[i] = lv;
}

// ---------------- gating ----------------
__global__ void k_init() {
    int i = threadIdx.x;
    if (i < NE) { g_cnt[i] = 0; g_fill[i] = 0; }
}

__global__ void k_gate(const float* __restrict__ x, const float* __restrict__ gw) {
    int gt = blockIdx.x * blockDim.x + threadIdx.x;
    int t = gt >> 5, lane = gt & 31;
    if (t >= NT) return;
    const float* xr = x + (size_t)t * HD;
    float acc[NE];
#pragma unroll
    for (int e = 0; e < NE; e++) acc[e] = 0.f;
    for (int i = lane; i < HD; i += 32) {
        float xv = xr[i];
#pragma unroll
        for (int e = 0; e < NE; e++) acc[e] += xv * gw[e * HD + i];
    }
#pragma unroll
    for (int e = 0; e < NE; e++)
#pragma unroll
        for (int o = 16; o > 0; o >>= 1)
            acc[e] += __shfl_down_sync(0xffffffffu, acc[e], o);
    if (lane == 0) {
        float m = acc[0];
#pragma unroll
        for (int e = 1; e < NE; e++) m = fmaxf(m, acc[e]);
        float p[NE], s = 0.f;
#pragma unroll
        for (int e = 0; e < NE; e++) { p[e] = expf(acc[e] - m); s += p[e]; }
        float inv = 1.f / s;
#pragma unroll
        for (int e = 0; e < NE; e++) p[e] *= inv;
        int i0 = 0; float v0 = p[0];
#pragma unroll
        for (int e = 1; e < NE; e++) if (p[e] > v0) { v0 = p[e]; i0 = e; }
        int i1 = -1; float v1 = -1.f;
#pragma unroll
        for (int e = 0; e < NE; e++) if (e != i0 && p[e] > v1) { v1 = p[e]; i1 = e; }
        float d = 1.f / (v0 + v1 + 1e-20f);
        g_tidx[t * 2 + 0] = i0; g_tw[t * 2 + 0] = v0 * d;
        g_tidx[t * 2 + 1] = i1; g_tw[t * 2 + 1] = v1 * d;
        atomicAdd(&g_cnt[i0], 1);
        atomicAdd(&g_cnt[i1], 1);
    }
}

__global__ void k_scan() {
    if (threadIdx.x == 0) {
        int acc = 0;
        for (int e = 0; e < NE; e++) {
            g_seg[e] = acc;
            acc += (g_cnt[e] + TMR - 1) / TMR * TMR;
        }
    }
}

__global__ void k_scatter() {
    int t = blockIdx.x * blockDim.x + threadIdx.x;
    if (t >= NT) return;
#pragma unroll
    for (int k = 0; k < 2; k++) {
        int e = g_tidx[t * 2 + k];
        float w = g_tw[t * 2 + k];
        int pos = atomicAdd(&g_fill[e], 1);
        g_btok[g_seg[e] + pos] = t;
        g_bw[g_seg[e] + pos] = w;
    }
}

__device__ __forceinline__ void find_expert(int row0, int& e_out, int& valid_out) {
    int e = -1, vr = 0;
    for (int i = 0; i < NE; i++) {
        int st = g_seg[i];
        int sz = (g_cnt[i] + TMR - 1) / TMR * TMR;
        if (row0 >= st && row0 < st + sz) { e = i; vr = g_cnt[i] - (row0 - st); break; }
    }
    e_out = e; valid_out = vr;
}

// ================= fused gate+up GEMM =================
// stage planes: Ah, Al, Gh, Gl, Uh, Ul; rows padded to 80B (conflict-free ldmatrix)
template <int ROUTED>
__global__ __launch_bounds__(256, 1)
void k_upgate() {
    extern __shared__ char smem[];
    uint32_t sb0 = smem_u32(smem);
    uint32_t sb = (sb0 + 127u) & ~127u;
    char* ctrlp = smem + (sb - sb0) + 3 * STG_UP;
    int* sh_meta = (int*)ctrlp;
    int* stok = (int*)(ctrlp + 16);

    int tid = threadIdx.x, lane = tid & 31, wid = tid >> 5;
    int wm = wid & 1, wn = wid >> 1;
    int row0 = blockIdx.y * TMR, col0 = blockIdx.x * TMR;

    int e = 0, nvalid = TMR;
    if (ROUTED) {
        if (tid == 0) {
            int ee, vv; find_expert(row0, ee, vv);
            sh_meta[0] = ee; sh_meta[1] = vv;
        }
        __syncthreads();
        e = sh_meta[0];
        int v = sh_meta[1];
        if (e < 0 || v <= 0) return;
        nvalid = v > TMR ? TMR : v;
        if (tid < TMR) stok[tid] = (tid < nvalid) ? g_btok[row0 + tid] : 0;
        __syncthreads();
    }

    // fill mapping: thread owns (row = tid>>1, 16-elem half q = tid&1)
    int frow = tid >> 1, q = tid & 1;
    int qe = q * 16;
    uint32_t dof = (uint32_t)frow * ROWB + (uint32_t)q * 32u;

    const uint16_t *pah, *pal, *pgh, *pgl, *puh, *pul;
    if (ROUTED) {
        int tok = stok[frow];
        pah = b_xh + (size_t)tok * HD; pal = b_xl + (size_t)tok * HD;
        size_t wo = (size_t)e * FF * HD + (size_t)(col0 + frow) * HD;
        pgh = b_wgh + wo; pgl = b_wgl + wo;
        puh = b_wuh + wo; pul = b_wul + wo;
    } else {
        pah = b_xh + (size_t)(row0 + frow) * HD; pal = b_xl + (size_t)(row0 + frow) * HD;
        size_t wo = (size_t)(col0 + frow) * HD;
        pgh = b_sgh + wo; pgl = b_sgl + wo;
        puh = b_suh + wo; pul = b_sul + wo;
    }

    auto fill = [&](int c) {
        int k = c * KCH + qe;
        uint32_t sg = sb + (uint32_t)(c % 3) * STG_UP + dof;
        cp2(sg + 0u * PL, pah + k);
        cp2(sg + 1u * PL, pal + k);
        cp2(sg + 2u * PL, pgh + k);
        cp2(sg + 3u * PL, pgl + k);
        cp2(sg + 4u * PL, puh + k);
        cp2(sg + 5u * PL, pul + k);
    };

    uint32_t a_off = (uint32_t)(wm * 64 + (lane & 15)) * ROWB + (uint32_t)((lane >> 4) * 16);
    uint32_t b_off = (uint32_t)(wn * 32 + ((lane >> 4) * 8) + (lane & 7)) * ROWB
                   + (uint32_t)(((lane >> 3) & 1) * 16);

    float accg[4][4][4], accu[4][4][4];
#pragma unroll
    for (int i = 0; i < 4; i++)
#pragma unroll
        for (int j = 0; j < 4; j++)
#pragma unroll
            for (int p = 0; p < 4; p++) { accg[i][j][p] = 0.f; accu[i][j][p] = 0.f; }

    const int NC = HD / KCH;
    fill(0); cp_commit();
    fill(1); cp_commit();

    for (int c = 0; c < NC; c++) {
        cp_wait<1>();
        __syncthreads();
        if (c + 2 < NC) fill(c + 2);
        cp_commit();
        uint32_t sg = sb + (uint32_t)(c % 3) * STG_UP;
#pragma unroll
        for (int s = 0; s < 2; s++) {
            uint32_t ka = a_off + (uint32_t)s * 32u;
            uint32_t kb = b_off + (uint32_t)s * 32u;
            uint32_t ah[4][4], al[4][4];
#pragma unroll
            for (int i = 0; i < 4; i++) {
                uint32_t o = ka + (uint32_t)i * (16u * ROWB);
                ldsm4(ah[i], sg + 0u * PL + o);
                ldsm4(al[i], sg + 1u * PL + o);
            }
            uint32_t bh[2][4], bl[2][4];
#pragma unroll
            for (int jj = 0; jj < 2; jj++) {
                uint32_t o = kb + (uint32_t)jj * (16u * ROWB);
                ldsm4(bh[jj], sg + 2u * PL + o);
                ldsm4(bl[jj], sg + 3u * PL + o);
            }
#pragma unroll
            for (int i = 0; i < 4; i++)
#pragma unroll
                for (int j = 0; j < 4; j++) {
                    const uint32_t* fh = &bh[j >> 1][(j & 1) * 2];
                    const uint32_t* fl = &bl[j >> 1][(j & 1) * 2];
                    mma16816(accg[i][j], ah[i], fh);
                    mma16816(accg[i][j], al[i], fh);
                    mma16816(accg[i][j], ah[i], fl);
                }
#pragma unroll
            for (int jj = 0; jj < 2; jj++) {
                uint32_t o = kb + (uint32_t)jj * (16u * ROWB);
                ldsm4(bh[jj], sg + 4u * PL + o);
                ldsm4(bl[jj], sg + 5u * PL + o);
            }
#pragma unroll
            for (int i = 0; i < 4; i++)
#pragma unroll
                for (int j = 0; j < 4; j++) {
                    const uint32_t* fh = &bh[j >> 1][(j & 1) * 2];
                    const uint32_t* fl = &bl[j >> 1][(j & 1) * 2];
                    mma16816(accu[i][j], ah[i], fh);
                    mma16816(accu[i][j], al[i], fh);
                    mma16816(accu[i][j], ah[i], fl);
                }
        }
    }

    // epilogue: silu(g)*u -> bf16 hi/lo h1
    const int LDC = ROUTED ? FF : FSS;
    uint16_t* dh = ROUTED ? b_h1h : b_h1sh;
    uint16_t* dl = ROUTED ? b_h1l : b_h1sl;
#pragma unroll
    for (int i = 0; i < 4; i++) {
        int rl0 = wm * 64 + i * 16 + (lane >> 2);
        int rl1 = rl0 + 8;
#pragma unroll
        for (int j = 0; j < 4; j++) {
            int cl = wn * 32 + j * 8 + (lane & 3) * 2;
            if (!ROUTED || rl0 < nvalid) {
                float g0 = accg[i][j][0], g1 = accg[i][j][1];
                float o0 = g0 / (1.f + __expf(-g0)) * accu[i][j][0];
                float o1 = g1 / (1.f + __expf(-g1)) * accu[i][j][1];
                split_store(dh, dl, ((size_t)(row0 + rl0) * LDC + col0 + cl) >> 1, o0, o1);
            }
            if (!ROUTED || rl1 < nvalid) {
                float g0 = accg[i][j][2], g1 = accg[i][j][3];
                float o0 = g0 / (1.f + __expf(-g0)) * accu[i][j][2];
                float o1 = g1 / (1.f + __expf(-g1)) * accu[i][j][3];
                split_store(dh, dl, ((size_t)(row0 + rl1) * LDC + col0 + cl) >> 1, o0, o1);
            }
        }
    }
}

// ================= down GEMM =================
// stage planes: Ah, Al, Bh, Bl
template <int ROUTED>
__global__ __launch_bounds__(256, 1)
void k_down(float* __restrict__ out) {
    extern __shared__ char smem[];
    uint32_t sb0 = smem_u32(smem);
    uint32_t sb = (sb0 + 127u) & ~127u;
    char* ctrlp = smem + (sb - sb0) + 3 * STG_DN;
    int* sh_meta = (int*)ctrlp;
    int* stok = (int*)(ctrlp + 16);
    float* swt = (float*)(ctrlp + 16 + 512);

    int tid = threadIdx.x, lane = tid & 31, wid = tid >> 5;
    int wm = wid & 1, wn = wid >> 1;
    int row0 = blockIdx.y * TMR, col0 = blockIdx.x * TMR;

    int e = 0, nvalid = TMR;
    if (ROUTED) {
        if (tid == 0) {
            int ee, vv; find_expert(row0, ee, vv);
            sh_meta[0] = ee; sh_meta[1] = vv;
        }
        __syncthreads();
        e = sh_meta[0];
        int v = sh_meta[1];
        if (e < 0 || v <= 0) return;
        nvalid = v > TMR ? TMR : v;
        if (tid < TMR) {
            bool ok = tid < nvalid;
            stok[tid] = ok ? g_btok[row0 + tid] : 0;
            swt[tid]  = ok ? g_bw[row0 + tid]   : 0.f;
        }
        __syncthreads();
    }

    const int KD = ROUTED ? FF : FSS;
    int frow = tid >> 1, q = tid & 1;
    int qe = q * 16;
    uint32_t dof = (uint32_t)frow * ROWB + (uint32_t)q * 32u;

    const uint16_t* pah = (ROUTED ? b_h1h : b_h1sh) + (size_t)(row0 + frow) * KD;
    const uint16_t* pal = (ROUTED ? b_h1l : b_h1sl) + (size_t)(row0 + frow) * KD;
    const uint16_t* pbh = (ROUTED ? b_wdh + (size_t)e * HD * FF : b_sdh)
                          + (size_t)(col0 + frow) * KD;
    const uint16_t* pbl = (ROUTED ? b_wdl + (size_t)e * HD * FF : b_sdl)
                          + (size_t)(col0 + frow) * KD;

    auto fill = [&](int c) {
        int k = c * KCH + qe;
        uint32_t sg = sb + (uint32_t)(c % 3) * STG_DN + dof;
        cp2(sg + 0u * PL, pah + k);
        cp2(sg + 1u * PL, pal + k);
        cp2(sg + 2u * PL, pbh + k);
        cp2(sg + 3u * PL, pbl + k);
    };

    uint32_t a_off = (uint32_t)(wm * 64 + (lane & 15)) * ROWB + (uint32_t)((lane >> 4) * 16);
    uint32_t b_off = (uint32_t)(wn * 32 + ((lane >> 4) * 8) + (lane & 7)) * ROWB
                   + (uint32_t)(((lane >> 3) & 1) * 16);

    float acc[4][4][4];
#pragma unroll
    for (int i = 0; i < 4; i++)
#pragma unroll
        for (int j = 0; j < 4; j++)
#pragma unroll
            for (int p = 0; p < 4; p++) acc[i][j][p] = 0.f;

    const int NC = KD / KCH;
    fill(0); cp_commit();
    fill(1); cp_commit();

    for (int c = 0; c < NC; c++) {
        cp_wait<1>();
        __syncthreads();
        if (c + 2 < NC) fill(c + 2);
        cp_commit();
        uint32_t sg = sb + (uint32_t)(c % 3) * STG_DN;
#pragma unroll
        for (int s = 0; s < 2; s++) {
            uint32_t ka = a_off + (uint32_t)s * 32u;
            uint32_t kb = b_off + (uint32_t)s * 32u;
            uint32_t ah[4][4], al[4][4];
#pragma unroll
            for (int i = 0; i < 4; i++) {
                uint32_t o = ka + (uint32_t)i * (16u * ROWB);
                ldsm4(ah[i], sg + 0u * PL + o);
                ldsm4(al[i], sg + 1u * PL + o);
            }
            uint32_t bh[2][4], bl[2][4];
#pragma unroll
            for (int jj = 0; jj < 2; jj++) {
                uint32_t o = kb + (uint32_t)jj * (16u * ROWB);
                ldsm4(bh[jj], sg + 2u * PL + o);
                ldsm4(bl[jj], sg + 3u * PL + o);
            }
#pragma unroll
            for (int i = 0; i < 4; i++)
#pragma unroll
                for (int j = 0; j < 4; j++) {
                    const uint32_t* fh = &bh[j >> 1][(j & 1) * 2];
                    const uint32_t* fl = &bl[j >> 1][(j & 1) * 2];
                    mma16816(acc[i][j], ah[i], fh);
                    mma16816(acc[i][j], al[i], fh);
                    mma16816(acc[i][j], ah[i], fl);
                }
        }
    }

    // epilogue
#pragma unroll
    for (int i = 0; i < 4; i++) {
        int rl0 = wm * 64 + i * 16 + (lane >> 2);
        int rl1 = rl0 + 8;
#pragma unroll
        for (int j = 0; j < 4; j++) {
            int cl = wn * 32 + j * 8 + (lane & 3) * 2;
            if (ROUTED) {
                if (rl0 < nvalid) {
                    float w = swt[rl0];
                    float* o = out + (size_t)stok[rl0] * HD + col0 + cl;
                    atomicAdd(&o[0], w * acc[i][j][0]);
                    atomicAdd(&o[1], w * acc[i][j][1]);
                }
                if (rl1 < nvalid) {
                    float w = swt[rl1];
                    float* o = out + (size_t)stok[rl1] * HD + col0 + cl;
                    atomicAdd(&o[0], w * acc[i][j][2]);
                    atomicAdd(&o[1], w * acc[i][j][3]);
                }
            } else {
                float2 v0; v0.x = acc[i][j][0]; v0.y = acc[i][j][1];
                float2 v1; v1.x = acc[i][j][2]; v1.y = acc[i][j][3];
                *(float2*)(out + (size_t)(row0 + rl0) * HD + col0 + cl) = v0;
                *(float2*)(out + (size_t)(row0 + rl1) * HD + col0 + cl) = v1;
            }
        }
    }
}

// ---------------- launch ----------------
extern "C" void kernel_launch(void* const* d_in, const int* in_sizes, int n_in,
                              void* d_out, int out_size) {
    const float* x   = (const float*)d_in[0];
    const float* gw  = (const float*)d_in[1];
    const float* wg  = (const float*)d_in[2];
    const float* wu  = (const float*)d_in[3];
    const float* wd  = (const float*)d_in[4];
    const float* swg = (const float*)d_in[5];
    const float* swu = (const float*)d_in[6];
    const float* swd = (const float*)d_in[7];
    float* out = (float*)d_out;

    cudaFuncSetAttribute(k_upgate<1>, cudaFuncAttributeMaxDynamicSharedMemorySize, UP_SMEM);
    cudaFuncSetAttribute(k_upgate<0>, cudaFuncAttributeMaxDynamicSharedMemorySize, UP_SMEM);
    cudaFuncSetAttribute(k_down<1>,   cudaFuncAttributeMaxDynamicSharedMemorySize, DN_SMEM);
    cudaFuncSetAttribute(k_down<0>,   cudaFuncAttributeMaxDynamicSharedMemorySize, DN_SMEM);

    k_init<<<1, 32>>>();
    k_gate<<<NT / 8, 256>>>(x, gw);
    k_scan<<<1, 32>>>();
    k_scatter<<<(NT + 255) / 256, 256>>>();

    // pre-convert everything to bf16 hi/lo
    {
        int n4x = NT * HD / 4;
        k_cvt<<<(n4x + 255) / 256, 256>>>(x, 0, n4x);
        int n4w = NE * FF * HD / 4;
        k_cvt<<<(n4w + 255) / 256, 256>>>(wg, 1, n4w);
        k_cvt<<<(n4w + 255) / 256, 256>>>(wu, 2, n4w);
        k_cvt<<<(n4w + 255) / 256, 256>>>(wd, 3, n4w);
        int n4s = FSS * HD / 4;
        k_cvt<<<(n4s + 255) / 256, 256>>>(swg, 4, n4s);
        k_cvt<<<(n4s + 255) / 256, 256>>>(swu, 5, n4s);
        k_cvt<<<(n4s + 255) / 256, 256>>>(swd, 6, n4s);
    }

    // shared expert first: its down-proj initializes `out` with plain stores
    k_upgate<0><<<dim3(FSS / TMR, NT / TMR), 256, UP_SMEM>>>();
    k_down<0><<<dim3(HD / TMR, NT / TMR), 256, DN_SMEM>>>(out);

    // routed experts accumulate on top via atomicAdd
    k_upgate<1><<<dim3(FF / TMR, CAPTILES), 256, UP_SMEM>>>();
    k_down<1><<<dim3(HD / TMR, CAPTILES), 256, DN_SMEM>>>(out);
}